// round 8
// baseline (speedup 1.0000x reference)
#include <cuda_runtime.h>
#include <cuda_pipeline.h>

// Problem constants
#define BB 16
#define KK 8
#define CC 64
#define LL 2048
#define CL (CC*LL)                 // 131072 elements per batch
#define CL4 (CL/4)                 // 32768 float4 per batch
#define TPB 256
#define BLK_PER_BATCH (CL4/TPB)    // 128 blocks per batch
#define NBLK (BB*BLK_PER_BATCH)    // 2048 blocks total
#define STAGES 4                   // cp.async pipeline depth (12KB/stage)

// Scratch for deterministic sldj reduction (allocations are forbidden).
__device__ float        g_partials[NBLK];
__device__ unsigned int g_counter = 0;

__device__ __forceinline__ float ftanh(float x) {
    float r; asm("tanh.approx.f32 %0, %1;" : "=f"(r) : "f"(x)); return r;
}

// 4 CTAs/SM: smem 48KB*4=192KB <= 228KB, regs cap 64 (no squeeze).
__global__ __launch_bounds__(TPB, 4) void coupling_fused(
    const float4* __restrict__ x4, const float4* __restrict__ a4,
    const float4* __restrict__ b4, const float4* __restrict__ pi4,
    const float4* __restrict__ mu4, const float4* __restrict__ s4,
    const float*  __restrict__ sldj_in,
    float4* __restrict__ out4, float* __restrict__ out_sldj)
{
    // [arr][stage][thread]: arr 0=pi, 1=mu, 2=s.  3*4*256*16B = 48KB.
    __shared__ __align__(16) float4 stg[3][STAGES][TPB];
    __shared__ float sred[TPB / 32];
    __shared__ int   s_last;

    const int tid = threadIdx.x;
    const int blk = blockIdx.x;
    const int bat = blk / BLK_PER_BATCH;
    const int j4  = (blk - bat * BLK_PER_BATCH) * TPB + tid;  // float4 idx in batch
    const int xi  = bat * CL4 + j4;              // float4 idx into [B,C,L]
    const int kb  = bat * KK * CL4 + j4;         // float4 idx into [B,K,C,L] (k=0)

    float4 xv = x4[xi];
    const float xh_[4] = {0.5f*xv.x, 0.5f*xv.y, 0.5f*xv.z, 0.5f*xv.w}; // x/2

    // ---- cp.async pipeline prologue: prefetch stages 0..STAGES-1 ----
#pragma unroll
    for (int st = 0; st < STAGES; st++) {
        __pipeline_memcpy_async(&stg[0][st][tid], &pi4[kb + st * CL4], 16);
        __pipeline_memcpy_async(&stg[1][st][tid], &mu4[kb + st * CL4], 16);
        __pipeline_memcpy_async(&stg[2][st][tid], &s4 [kb + st * CL4], 16);
        __pipeline_commit();
    }

    // Fused single pass, tanh formulation:
    //   w = exp(pi); es = exp(-s); z = (x-mu)*es; t = tanh(z/2)
    //   sigmoid(z)  = 0.5*(1+t);  sig*(1-sig) = 0.25*(1-t^2)
    //   W   = sum w
    //   S1t = sum w*t            -> S1 = 0.5*(W+S1t) = sum w*sig  -> u = S1/W
    //   S2  = sum w*es*(1-t^2)   -> pdf = 0.25*S2/W
    float W_[4]  = {0, 0, 0, 0};
    float S1t[4] = {0, 0, 0, 0};
    float S2_[4] = {0, 0, 0, 0};
#pragma unroll
    for (int k = 0; k < KK; k++) {
        // Commits so far = STAGES + k; leaving STAGES-1 pending => group k done.
        __pipeline_wait_prior(STAGES - 1);
        const int st = k % STAGES;
        float4 pv = stg[0][st][tid];
        float4 mv = stg[1][st][tid];
        float4 sv = stg[2][st][tid];
        // Refill this slot for iteration k+STAGES (reads above issue first).
        if (k + STAGES < KK) {
            __pipeline_memcpy_async(&stg[0][st][tid], &pi4[kb + (k + STAGES) * CL4], 16);
            __pipeline_memcpy_async(&stg[1][st][tid], &mu4[kb + (k + STAGES) * CL4], 16);
            __pipeline_memcpy_async(&stg[2][st][tid], &s4 [kb + (k + STAGES) * CL4], 16);
        }
        __pipeline_commit();   // one group per iter keeps wait accounting fixed

        float pi_l[4] = {pv.x, pv.y, pv.z, pv.w};
        float mu_l[4] = {mv.x, mv.y, mv.z, mv.w};
        float s_l[4]  = {sv.x, sv.y, sv.z, sv.w};
#pragma unroll
        for (int l = 0; l < 4; l++) {
            float w   = __expf(pi_l[l]);
            float es  = __expf(-s_l[l]);
            float z2  = (xh_[l] - 0.5f * mu_l[l]) * es;   // z/2
            float t   = ftanh(z2);
            float t2m = fmaf(-t, t, 1.0f);                // 1 - t^2
            W_[l]  += w;
            S1t[l] = fmaf(w, t, S1t[l]);
            S2_[l] = fmaf(w * es, t2m, S2_[l]);
        }
    }

    // Per-element tensors needed only in the epilogue.
    float4 av = a4[xi];
    float4 bv = b4[xi];
    const float a_l[4] = {av.x, av.y, av.z, av.w};
    const float b_l[4] = {bv.x, bv.y, bv.z, bv.w};

    float o_[4];
    float ldj = 0.0f;
#pragma unroll
    for (int l = 0; l < 4; l++) {
        float W   = W_[l];
        float S1  = 0.5f * (W + S1t[l]);          // sum w*sig
        // clamp u=S1/W to [1e-7, 1-1e-7] without dividing
        float S1c = fminf(fmaxf(S1, W * 1e-7f), W * (1.0f - 1e-7f));
        float D   = W - S1c;                      // W*(1-u)
        float L1  = __logf(S1c);
        float L2  = __logf(D);
        // scale = sigmoid(a+2) + (1 - sigmoid(2)) = 0.6192029 + 0.5*tanh((a+2)/2)
        float ta    = ftanh(fmaf(0.5f, a_l[l], 1.0f));
        float scale = fmaf(0.5f, ta, 0.61920292202211755f);
        // ldj_el = log(pdf) - log u - log(1-u) + log(scale)
        //        = log(0.25*S2*W*scale) - L1 - L2
        float Lp  = __logf(0.25f * S2_[l] * W * scale);
        float y   = L1 - L2;                      // logit(u)
        o_[l] = (y + b_l[l]) * scale;
        ldj  += Lp - L1 - L2;
    }
    __stcs(&out4[xi], make_float4(o_[0], o_[1], o_[2], o_[3]));

    // ---- deterministic block reduction of ldj -> g_partials[blk] ----
#pragma unroll
    for (int off = 16; off; off >>= 1)
        ldj += __shfl_down_sync(0xffffffffu, ldj, off);
    const int wid = tid >> 5, lid = tid & 31;
    if (lid == 0) sred[wid] = ldj;
    __syncthreads();
    if (tid == 0) {
        float v = 0.0f;
#pragma unroll
        for (int w = 0; w < TPB / 32; w++) v += sred[w];
        g_partials[blk] = v;
        __threadfence();
        unsigned int old = atomicAdd(&g_counter, 1u);
        s_last = (old == NBLK - 1);
    }
    __syncthreads();

    // ---- last block performs the final deterministic reduction ----
    if (s_last) {
        // 8 warps, warp w reduces batches w and w+8 (128 partials each).
        for (int b = wid; b < BB; b += TPB / 32) {
            const float* p = g_partials + b * BLK_PER_BATCH;
            float v = p[lid] + p[lid + 32] + p[lid + 64] + p[lid + 96];
#pragma unroll
            for (int off = 16; off; off >>= 1)
                v += __shfl_down_sync(0xffffffffu, v, off);
            if (lid == 0) out_sldj[b] = sldj_in[b] + v;
        }
        if (tid == 0) g_counter = 0;   // reset for next graph replay
    }
}

extern "C" void kernel_launch(void* const* d_in, const int* in_sizes, int n_in,
                              void* d_out, int out_size)
{
    const float4* x4  = (const float4*)d_in[0];  // x_change [B,C,L]
    const float4* a4  = (const float4*)d_in[1];  // a        [B,C,L]
    const float4* b4  = (const float4*)d_in[2];  // b        [B,C,L]
    const float4* pi4 = (const float4*)d_in[3];  // pi       [B,K,C,L]
    const float4* mu4 = (const float4*)d_in[4];  // mu       [B,K,C,L]
    const float4* s4  = (const float4*)d_in[5];  // s        [B,K,C,L]
    const float*  sldj = (const float*)d_in[6];  // sldj     [B]

    float* out = (float*)d_out;                  // [B*C*L] out, then [B] sldj_out

    coupling_fused<<<NBLK, TPB>>>(x4, a4, b4, pi4, mu4, s4, sldj,
                                  (float4*)out, out + (size_t)BB * CL);
}

// round 15
// speedup vs baseline: 1.0587x; 1.0587x over previous
#include <cuda_runtime.h>
#include <cuda_pipeline.h>

// Problem constants
#define BB 16
#define KK 8
#define CC 64
#define LL 2048
#define CL (CC*LL)                 // 131072 elements per batch
#define CL4 (CL/4)                 // 32768 float4 per batch
#define TPB 256
#define BLK_PER_BATCH (CL4/TPB)    // 128 blocks per batch
#define NBLK (BB*BLK_PER_BATCH)    // 2048 blocks total
#define STAGES 3                   // cp.async pipeline depth (12KB/stage)

// Scratch for deterministic sldj reduction (allocations are forbidden).
__device__ float        g_partials[NBLK];
__device__ unsigned int g_counter = 0;

__device__ __forceinline__ float ftanh(float x) {
    float r; asm("tanh.approx.f32 %0, %1;" : "=f"(r) : "f"(x)); return r;
}

// 5 CTAs/SM: smem 45KB*5=225KB <= 228KB, regs <= 51. 40/64 warps resident.
__global__ __launch_bounds__(TPB, 5) void coupling_fused(
    const float4* __restrict__ x4, const float4* __restrict__ a4,
    const float4* __restrict__ b4, const float4* __restrict__ pi4,
    const float4* __restrict__ mu4, const float4* __restrict__ s4,
    const float*  __restrict__ sldj_in,
    float4* __restrict__ out4, float* __restrict__ out_sldj)
{
    // [arr][stage][thread]: arr 0=pi, 1=mu, 2=s. 3*3*256*16B = 36KB.
    __shared__ __align__(16) float4 stg[3][STAGES][TPB];
    // a/b staged through the ring too (epilogue-only use): 2*256*16B = 8KB.
    __shared__ __align__(16) float4 stab[2][TPB];
    __shared__ float sred[TPB / 32];
    __shared__ int   s_last;

    const int tid = threadIdx.x;
    const int blk = blockIdx.x;
    const int bat = blk / BLK_PER_BATCH;
    const int j4  = (blk - bat * BLK_PER_BATCH) * TPB + tid;  // float4 idx in batch
    const int xi  = bat * CL4 + j4;              // float4 idx into [B,C,L]
    const int kb  = bat * KK * CL4 + j4;         // float4 idx into [B,K,C,L] (k=0)

    // x needed at k=0: plain LDG, overlaps the prologue cp.asyncs.
    float4 xv = x4[xi];
    const float xh_[4] = {0.5f*xv.x, 0.5f*xv.y, 0.5f*xv.z, 0.5f*xv.w}; // x/2

    // ---- cp.async prologue: stages 0..2; a/b attached to the last group ----
#pragma unroll
    for (int st = 0; st < STAGES; st++) {
        __pipeline_memcpy_async(&stg[0][st][tid], &pi4[kb + st * CL4], 16);
        __pipeline_memcpy_async(&stg[1][st][tid], &mu4[kb + st * CL4], 16);
        __pipeline_memcpy_async(&stg[2][st][tid], &s4 [kb + st * CL4], 16);
        if (st == STAGES - 1) {
            __pipeline_memcpy_async(&stab[0][tid], &a4[xi], 16);
            __pipeline_memcpy_async(&stab[1][tid], &b4[xi], 16);
        }
        __pipeline_commit();
    }

    // Fused single pass, tanh formulation:
    //   w = exp(pi); es = exp(-s); z = (x-mu)*es; t = tanh(z/2)
    //   sigmoid(z)  = 0.5*(1+t);  sig*(1-sig) = 0.25*(1-t^2)
    //   W = sum w; S1t = sum w*t; S2 = sum w*es*(1-t^2)
    float W_[4]  = {0, 0, 0, 0};
    float S1t[4] = {0, 0, 0, 0};
    float S2_[4] = {0, 0, 0, 0};
#pragma unroll
    for (int k = 0; k < KK; k++) {
        // Commits so far = STAGES + k; leaving STAGES-1 pending => group k done.
        __pipeline_wait_prior(STAGES - 1);
        const int st = k % STAGES;
        float4 pv = stg[0][st][tid];
        float4 mv = stg[1][st][tid];
        float4 sv = stg[2][st][tid];
        // Refill this slot for iteration k+STAGES (reads above issue first).
        if (k + STAGES < KK) {
            __pipeline_memcpy_async(&stg[0][st][tid], &pi4[kb + (k + STAGES) * CL4], 16);
            __pipeline_memcpy_async(&stg[1][st][tid], &mu4[kb + (k + STAGES) * CL4], 16);
            __pipeline_memcpy_async(&stg[2][st][tid], &s4 [kb + (k + STAGES) * CL4], 16);
        }
        __pipeline_commit();   // one group per iter keeps wait accounting fixed

        float pi_l[4] = {pv.x, pv.y, pv.z, pv.w};
        float mu_l[4] = {mv.x, mv.y, mv.z, mv.w};
        float s_l[4]  = {sv.x, sv.y, sv.z, sv.w};
#pragma unroll
        for (int l = 0; l < 4; l++) {
            float w   = __expf(pi_l[l]);
            float es  = __expf(-s_l[l]);
            float z2  = (xh_[l] - 0.5f * mu_l[l]) * es;   // z/2
            float t   = ftanh(z2);
            float t2m = fmaf(-t, t, 1.0f);                // 1 - t^2
            W_[l]  += w;
            S1t[l] = fmaf(w, t, S1t[l]);
            S2_[l] = fmaf(w * es, t2m, S2_[l]);
        }
    }

    // All groups (incl. the a/b group) complete; reads below are smem-only.
    __pipeline_wait_prior(0);
    float4 av = stab[0][tid];
    float4 bv = stab[1][tid];
    const float a_l[4] = {av.x, av.y, av.z, av.w};
    const float b_l[4] = {bv.x, bv.y, bv.z, bv.w};

    float o_[4];
    float ldj = 0.0f;
#pragma unroll
    for (int l = 0; l < 4; l++) {
        float W   = W_[l];
        float S1  = 0.5f * (W + S1t[l]);          // sum w*sig
        // clamp u=S1/W to [1e-7, 1-1e-7] without dividing
        float S1c = fminf(fmaxf(S1, W * 1e-7f), W * (1.0f - 1e-7f));
        float D   = W - S1c;                      // W*(1-u)
        float L1  = __logf(S1c);
        float L2  = __logf(D);
        // scale = sigmoid(a+2) + (1-sigmoid(2)) = 0.6192029 + 0.5*tanh((a+2)/2)
        float ta    = ftanh(fmaf(0.5f, a_l[l], 1.0f));
        float scale = fmaf(0.5f, ta, 0.61920292202211755f);
        // ldj_el = log(pdf) - log u - log(1-u) + log(scale)
        //        = log(0.25*S2*W*scale) - L1 - L2
        float Lp  = __logf(0.25f * S2_[l] * W * scale);
        float y   = L1 - L2;                      // logit(u)
        o_[l] = (y + b_l[l]) * scale;
        ldj  += Lp - L1 - L2;
    }
    __stcs(&out4[xi], make_float4(o_[0], o_[1], o_[2], o_[3]));

    // ---- deterministic block reduction of ldj -> g_partials[blk] ----
#pragma unroll
    for (int off = 16; off; off >>= 1)
        ldj += __shfl_down_sync(0xffffffffu, ldj, off);
    const int wid = tid >> 5, lid = tid & 31;
    if (lid == 0) sred[wid] = ldj;
    __syncthreads();
    if (tid == 0) {
        float v = 0.0f;
#pragma unroll
        for (int w = 0; w < TPB / 32; w++) v += sred[w];
        g_partials[blk] = v;
        __threadfence();
        unsigned int old = atomicAdd(&g_counter, 1u);
        s_last = (old == NBLK - 1);
    }
    __syncthreads();

    // ---- last block performs the final deterministic reduction ----
    if (s_last) {
        // 8 warps, warp w reduces batches w and w+8 (128 partials each).
        for (int b = wid; b < BB; b += TPB / 32) {
            const float* p = g_partials + b * BLK_PER_BATCH;
            float v = p[lid] + p[lid + 32] + p[lid + 64] + p[lid + 96];
#pragma unroll
            for (int off = 16; off; off >>= 1)
                v += __shfl_down_sync(0xffffffffu, v, off);
            if (lid == 0) out_sldj[b] = sldj_in[b] + v;
        }
        if (tid == 0) g_counter = 0;   // reset for next graph replay
    }
}

extern "C" void kernel_launch(void* const* d_in, const int* in_sizes, int n_in,
                              void* d_out, int out_size)
{
    const float4* x4  = (const float4*)d_in[0];  // x_change [B,C,L]
    const float4* a4  = (const float4*)d_in[1];  // a        [B,C,L]
    const float4* b4  = (const float4*)d_in[2];  // b        [B,C,L]
    const float4* pi4 = (const float4*)d_in[3];  // pi       [B,K,C,L]
    const float4* mu4 = (const float4*)d_in[4];  // mu       [B,K,C,L]
    const float4* s4  = (const float4*)d_in[5];  // s        [B,K,C,L]
    const float*  sldj = (const float*)d_in[6];  // sldj     [B]

    float* out = (float*)d_out;                  // [B*C*L] out, then [B] sldj_out

    coupling_fused<<<NBLK, TPB>>>(x4, a4, b4, pi4, mu4, s4, sldj,
                                  (float4*)out, out + (size_t)BB * CL);
}